// round 16
// baseline (speedup 1.0000x reference)
#include <cuda_runtime.h>
#include <cuda_bf16.h>
#include <cuda_fp16.h>
#include <math.h>
#include <stdint.h>

#define T_TOK 4096
#define DIM   2048
#define H     128
#define NCH   8
#define NQT   32
#define SKS   40       // qkv smem stride (bf16)
#define SKS2  136      // attn smem stride (bf16/half)
#define SCALE_F 0.08838834764831843f
#define XN (T_TOK * DIM)
#define WN (H * DIM)

// ---------------- device scratch -------------------------------------------
__device__ __nv_bfloat16 g_Xhi[T_TOK * DIM];
__device__ __nv_bfloat16 g_Xlo[T_TOK * DIM];
__device__ __nv_bfloat16 g_Whi[3 * H * DIM];
__device__ __nv_bfloat16 g_Wlo[3 * H * DIM];
__device__ float g_part[9 * T_TOK * H];
__device__ __nv_bfloat16 g_Qhi[T_TOK * H], g_Qlo[T_TOK * H];
__device__ __nv_bfloat16 g_Khi[T_TOK * H], g_Klo[T_TOK * H];
__device__ __half        g_Vh[T_TOK * H];
__device__ float g_pO[NQT * NCH * 128 * H];
__device__ float g_pm[NQT * NCH * 128];
__device__ float g_pl[NQT * NCH * 128];
__device__ int   g_cnt[NQT];

// ---------------- helpers ---------------------------------------------------
__device__ __forceinline__ uint32_t smem_u32(const void* p) {
    uint32_t a;
    asm("{ .reg .u64 t; cvta.to.shared.u64 t, %1; cvt.u32.u64 %0, t; }"
        : "=r"(a) : "l"(p));
    return a;
}
__device__ __forceinline__ void cp16(uint32_t d, const void* s) {
    asm volatile("cp.async.cg.shared.global [%0], [%1], 16;" :: "r"(d), "l"(s));
}
#define CP_COMMIT() asm volatile("cp.async.commit_group;" ::: "memory")
#define CP_WAIT(n)  asm volatile("cp.async.wait_group %0;" :: "n"(n) : "memory")

__device__ __forceinline__ void mma16816(float* c, const uint32_t* a, const uint32_t* b)
{
    asm volatile(
        "mma.sync.aligned.m16n8k16.row.col.f32.bf16.bf16.f32 "
        "{%0,%1,%2,%3}, {%4,%5,%6,%7}, {%8,%9}, {%0,%1,%2,%3};"
        : "+f"(c[0]), "+f"(c[1]), "+f"(c[2]), "+f"(c[3])
        : "r"(a[0]), "r"(a[1]), "r"(a[2]), "r"(a[3]), "r"(b[0]), "r"(b[1]));
}
__device__ __forceinline__ void mma16816h(float* c, const uint32_t* a, const uint32_t* b)
{
    asm volatile(
        "mma.sync.aligned.m16n8k16.row.col.f32.f16.f16.f32 "
        "{%0,%1,%2,%3}, {%4,%5,%6,%7}, {%8,%9}, {%0,%1,%2,%3};"
        : "+f"(c[0]), "+f"(c[1]), "+f"(c[2]), "+f"(c[3])
        : "r"(a[0]), "r"(a[1]), "r"(a[2]), "r"(a[3]), "r"(b[0]), "r"(b[1]));
}
__device__ __forceinline__ void ldsm4(uint32_t* r, uint32_t a)
{
    asm volatile("ldmatrix.sync.aligned.m8n8.x4.shared.b16 {%0,%1,%2,%3}, [%4];"
                 : "=r"(r[0]), "=r"(r[1]), "=r"(r[2]), "=r"(r[3]) : "r"(a));
}
__device__ __forceinline__ void ldsm4t(uint32_t* r, uint32_t a)
{
    asm volatile("ldmatrix.sync.aligned.m8n8.x4.trans.shared.b16 {%0,%1,%2,%3}, [%4];"
                 : "=r"(r[0]), "=r"(r[1]), "=r"(r[2]), "=r"(r[3]) : "r"(a));
}
__device__ __forceinline__ uint32_t pack_hi(float x, float y, uint32_t& lo)
{
    __nv_bfloat16 hx = __float2bfloat16(x);
    __nv_bfloat16 hy = __float2bfloat16(y);
    __nv_bfloat16 lx = __float2bfloat16(x - __bfloat162float(hx));
    __nv_bfloat16 ly = __float2bfloat16(y - __bfloat162float(hy));
    __nv_bfloat162 l2 = __halves2bfloat162(lx, ly);
    lo = *(uint32_t*)&l2;
    __nv_bfloat162 h2 = __halves2bfloat162(hx, hy);
    return *(uint32_t*)&h2;
}
__device__ __forceinline__ uint32_t pack_h2(float x, float y)
{
    __half2 t = __floats2half2_rn(x, y);
    return *(uint32_t*)&t;
}

// ---------------------------------------------------------------------------
// Fused fp32 -> (bf16 hi, lo) split for X, Wq, Wk, Wv in ONE launch.
// Also resets the per-qt combine counters.
// grid = (XN + 3*WN) / 2048 = 4480 blocks.
// ---------------------------------------------------------------------------
__global__ __launch_bounds__(256) void cvt_all_kernel(
    const float* __restrict__ x,  const float* __restrict__ wq,
    const float* __restrict__ wk, const float* __restrict__ wv)
{
    if (blockIdx.x == 0 && threadIdx.x < NQT) g_cnt[threadIdx.x] = 0;

    int i = (blockIdx.x * 256 + threadIdx.x) * 8;
    const float* src;
    __nv_bfloat16 *hi, *lo;
    if (i < XN) {
        src = x + i;
        hi = g_Xhi + i; lo = g_Xlo + i;
    } else {
        int j = i - XN;
        int widx = j / WN;
        int off = j - widx * WN;
        src = (widx == 0 ? wq : widx == 1 ? wk : wv) + off;
        hi = g_Whi + (size_t)widx * WN + off;
        lo = g_Wlo + (size_t)widx * WN + off;
    }
    float4 a = *(const float4*)src;
    float4 b = *(const float4*)(src + 4);
    float xs[8] = {a.x, a.y, a.z, a.w, b.x, b.y, b.z, b.w};
    uint4 hv, lv;
    uint32_t* hp = (uint32_t*)&hv;
    uint32_t* lp = (uint32_t*)&lv;
    #pragma unroll
    for (int j2 = 0; j2 < 4; j2++)
        hp[j2] = pack_hi(xs[2 * j2], xs[2 * j2 + 1], lp[j2]);
    *(uint4*)hi = hv;
    *(uint4*)lo = lv;
}

// ---------------------------------------------------------------------------
// QKV GEMM, bf16x3, K-split-3, cp.async double buffer, ldmatrix frags.
// grid (32, 3, 3).
// ---------------------------------------------------------------------------
#define QKV_STAGE_ELEMS (4 * 128 * SKS)

__global__ __launch_bounds__(256, 2) void qkv_mma_kernel()
{
    extern __shared__ __nv_bfloat16 qsm[];

    const int tid = threadIdx.x;
    const int lid = tid & 31;
    const int wid = tid >> 5;
    const int wm  = wid & 3;
    const int wn  = wid >> 2;
    const int m0  = blockIdx.x * 128;
    const int widx = blockIdx.y;
    const int z    = blockIdx.z;

    const int kbeg = (z == 0) ? 0 : (z == 1) ? 22 : 43;
    const int nkc  = (z == 0) ? 22 : 21;

    const __nv_bfloat16* Ahi = g_Xhi + (size_t)m0 * DIM;
    const __nv_bfloat16* Alo = g_Xlo + (size_t)m0 * DIM;
    const __nv_bfloat16* Bhi = g_Whi + (size_t)widx * H * DIM;
    const __nv_bfloat16* Blo = g_Wlo + (size_t)widx * H * DIM;

    const uint32_t sbase = smem_u32(qsm);
    const uint32_t MAT = 128 * SKS * 2;

    auto issue = [&](int i) {
        uint32_t sb = sbase + (uint32_t)(i & 1) * (4 * MAT);
        int kglob = (kbeg + i) * 32;
        #pragma unroll
        for (int g = 0; g < 2; g++) {
            int idx = tid + g * 256;
            int row = idx >> 2, c8 = (idx & 3) * 8;
            size_t go = (size_t)row * DIM + kglob + c8;
            uint32_t dof = (uint32_t)(row * SKS + c8) * 2;
            cp16(sb + dof,           Ahi + go);
            cp16(sb + MAT + dof,     Alo + go);
            cp16(sb + 2 * MAT + dof, Bhi + go);
            cp16(sb + 3 * MAT + dof, Blo + go);
        }
    };

    float acc[2][8][4];
    #pragma unroll
    for (int im = 0; im < 2; im++)
        #pragma unroll
        for (int in = 0; in < 8; in++)
            #pragma unroll
            for (int q = 0; q < 4; q++) acc[im][in][q] = 0.f;

    issue(0); CP_COMMIT();
    issue(1); CP_COMMIT();

    for (int i = 0; i < nkc; i++) {
        CP_WAIT(1);
        __syncthreads();

        const uint32_t uSt = sbase + (uint32_t)(i & 1) * (4 * MAT);
        const uint32_t uAh = uSt, uAl = uSt + MAT;
        const uint32_t uBh = uSt + 2 * MAT, uBl = uSt + 3 * MAT;

        #pragma unroll
        for (int ks = 0; ks < 2; ks++) {
            const int k0 = ks * 16;
            const uint32_t lrow = (lid & 15);
            const uint32_t lcol = k0 + ((lid >> 4) << 3);
            uint32_t ah[2][4], al[2][4];
            #pragma unroll
            for (int im = 0; im < 2; im++) {
                uint32_t aoff = ((wm * 32 + im * 16 + lrow) * SKS + lcol) * 2;
                ldsm4(ah[im], uAh + aoff);
                ldsm4(al[im], uAl + aoff);
            }
            #pragma unroll
            for (int np = 0; np < 4; np++) {
                uint32_t boff = ((wn * 64 + np * 16 + lrow) * SKS + lcol) * 2;
                uint32_t bh4[4], bl4[4];
                ldsm4(bh4, uBh + boff);
                ldsm4(bl4, uBl + boff);
                uint32_t b0h[2] = {bh4[0], bh4[2]}, b1h[2] = {bh4[1], bh4[3]};
                uint32_t b0l[2] = {bl4[0], bl4[2]}, b1l[2] = {bl4[1], bl4[3]};
                #pragma unroll
                for (int im = 0; im < 2; im++) {
                    mma16816(acc[im][2 * np],     ah[im], b0h);
                    mma16816(acc[im][2 * np],     ah[im], b0l);
                    mma16816(acc[im][2 * np],     al[im], b0h);
                    mma16816(acc[im][2 * np + 1], ah[im], b1h);
                    mma16816(acc[im][2 * np + 1], ah[im], b1l);
                    mma16816(acc[im][2 * np + 1], al[im], b1h);
                }
            }
        }
        __syncthreads();
        if (i + 2 < nkc) issue(i + 2);
        CP_COMMIT();
    }

    float* P = g_part + (size_t)(widx * 3 + z) * T_TOK * H + (size_t)m0 * H;
    #pragma unroll
    for (int im = 0; im < 2; im++) {
        int r0 = wm * 32 + im * 16 + (lid >> 2);
        #pragma unroll
        for (int in = 0; in < 8; in++) {
            int c0 = wn * 64 + in * 8 + (lid & 3) * 2;
            *(float2*)&P[(size_t)r0 * H + c0] =
                make_float2(acc[im][in][0], acc[im][in][1]);
            *(float2*)&P[(size_t)(r0 + 8) * H + c0] =
                make_float2(acc[im][in][2], acc[im][in][3]);
        }
    }
}

// ---------------------------------------------------------------------------
// Reduce K-split partials -> Q/K bf16 hi/lo (Q scaled), V fp16.
// ---------------------------------------------------------------------------
__global__ __launch_bounds__(256) void qkv_reduce_kernel()
{
    const int per = T_TOK * H / 4;
    int i4 = blockIdx.x * 256 + threadIdx.x;
    int widx = i4 / per;
    int off = (i4 - widx * per) * 4;
    const float* p0 = g_part + (size_t)(widx * 3 + 0) * (T_TOK * H) + off;
    const float* p1 = g_part + (size_t)(widx * 3 + 1) * (T_TOK * H) + off;
    const float* p2 = g_part + (size_t)(widx * 3 + 2) * (T_TOK * H) + off;
    float4 a = *(const float4*)p0;
    float4 b = *(const float4*)p1;
    float4 c = *(const float4*)p2;
    float v0 = a.x + b.x + c.x, v1 = a.y + b.y + c.y;
    float v2 = a.z + b.z + c.z, v3 = a.w + b.w + c.w;
    if (widx == 2) {
        *(uint32_t*)&g_Vh[off]     = pack_h2(v0, v1);
        *(uint32_t*)&g_Vh[off + 2] = pack_h2(v2, v3);
    } else {
        float sc = (widx == 0) ? SCALE_F : 1.f;
        v0 *= sc; v1 *= sc; v2 *= sc; v3 *= sc;
        __nv_bfloat16* Ch = widx ? g_Khi : g_Qhi;
        __nv_bfloat16* Cl = widx ? g_Klo : g_Qlo;
        uint32_t lo0, lo1;
        uint32_t h0 = pack_hi(v0, v1, lo0);
        uint32_t h1 = pack_hi(v2, v3, lo1);
        *(uint32_t*)&Ch[off]     = h0;
        *(uint32_t*)&Cl[off]     = lo0;
        *(uint32_t*)&Ch[off + 2] = h1;
        *(uint32_t*)&Cl[off + 2] = lo1;
    }
}

// ---------------------------------------------------------------------------
// Split-KV causal flash attention with in-kernel combine (last block per qt).
// Q frags in registers; K,V double-buffered, issued two tiles ahead.
// ---------------------------------------------------------------------------
#define TIL 34816u

__device__ __forceinline__ void attn_issue_tile(uint32_t dst_base,
                                                const void* src_base, int tid)
{
    #pragma unroll
    for (int j = 0; j < 8; j++) {
        int idx = tid + j * 256;
        int row = idx >> 4, c8 = (idx & 15) * 8;
        cp16(dst_base + (uint32_t)(row * SKS2 + c8) * 2,
             (const char*)src_base + ((size_t)row * H + c8) * 2);
    }
}

__global__ __launch_bounds__(256) void attn_partial_kernel(float* __restrict__ out)
{
    const int qt = blockIdx.x;
    const int ci = blockIdx.y;
    const int n_kt = qt + 1;
    const int kt0 = ci * 4;
    if (kt0 >= n_kt) return;
    const int kt1 = (kt0 + 4 < n_kt) ? kt0 + 4 : n_kt;
    const int n_ch = (n_kt + 3) >> 2;

    extern __shared__ char asm_[];
    const uint32_t base = smem_u32(asm_);
    __shared__ int sm_last;

    const int tid = threadIdx.x;
    const int wid = tid >> 5;
    const int lid = tid & 31;
    const int qr  = lid >> 2;
    const int qc  = lid & 3;
    const uint32_t lrow = (lid & 15);
    const uint32_t lcsh = ((lid >> 4) << 3);

    // ---- prologue: Q -> smem -> registers ----
    attn_issue_tile(base,           g_Qhi + (size_t)qt * 128 * H, tid);
    attn_issue_tile(base + 2 * TIL, g_Qlo + (size_t)qt * 128 * H, tid);
    CP_COMMIT();
    CP_WAIT(0);
    __syncthreads();

    uint32_t qfh[8][4], qfl[8][4];
    #pragma unroll
    for (int ks = 0; ks < 8; ks++) {
        uint32_t qoff = ((wid * 16 + lrow) * SKS2 + ks * 16 + lcsh) * 2;
        ldsm4(qfh[ks], base + qoff);
        ldsm4(qfl[ks], base + 2 * TIL + qoff);
    }
    __syncthreads();

    // ---- issue G(kt0) and G(kt0+1) ----
    attn_issue_tile(base,           g_Khi + (size_t)kt0 * 128 * H, tid);
    attn_issue_tile(base + 2 * TIL, g_Klo + (size_t)kt0 * 128 * H, tid);
    attn_issue_tile(base + 4 * TIL, g_Vh  + (size_t)kt0 * 128 * H, tid);
    CP_COMMIT();
    if (kt0 + 1 < kt1) {
        attn_issue_tile(base + TIL,     g_Khi + (size_t)(kt0 + 1) * 128 * H, tid);
        attn_issue_tile(base + 3 * TIL, g_Klo + (size_t)(kt0 + 1) * 128 * H, tid);
        attn_issue_tile(base + 5 * TIL, g_Vh  + (size_t)(kt0 + 1) * 128 * H, tid);
    }
    CP_COMMIT();

    float o[16][4];
    #pragma unroll
    for (int nt = 0; nt < 16; nt++)
        #pragma unroll
        for (int q = 0; q < 4; q++) o[nt][q] = 0.f;
    float mi0 = -INFINITY, mi1 = -INFINITY, li0 = 0.f, li1 = 0.f;

    for (int kt = kt0; kt < kt1; kt++) {
        const uint32_t b = (uint32_t)(kt - kt0) & 1;
        const uint32_t uKh = base + b * TIL;
        const uint32_t uKl = base + (2 + b) * TIL;
        const uint32_t uV  = base + (4 + b) * TIL;

        CP_WAIT(1);
        __syncthreads();

        // ---- S = Q K^T (bf16x3, Q from regs) ----
        float s[16][4];
        #pragma unroll
        for (int nt = 0; nt < 16; nt++)
            #pragma unroll
            for (int q = 0; q < 4; q++) s[nt][q] = 0.f;

        #pragma unroll
        for (int ks = 0; ks < 8; ks++) {
            const uint32_t lcol = ks * 16 + lcsh;
            #pragma unroll
            for (int np = 0; np < 8; np++) {
                uint32_t koff = ((np * 16 + lrow) * SKS2 + lcol) * 2;
                uint32_t bh4[4], bl4[4];
                ldsm4(bh4, uKh + koff);
                ldsm4(bl4, uKl + koff);
                uint32_t b0h[2] = {bh4[0], bh4[2]}, b1h[2] = {bh4[1], bh4[3]};
                uint32_t b0l[2] = {bl4[0], bl4[2]}, b1l[2] = {bl4[1], bl4[3]};
                mma16816(s[2 * np],     qfh[ks], b0h);
                mma16816(s[2 * np],     qfh[ks], b0l);
                mma16816(s[2 * np],     qfl[ks], b0h);
                mma16816(s[2 * np + 1], qfh[ks], b1h);
                mma16816(s[2 * np + 1], qfh[ks], b1l);
                mma16816(s[2 * np + 1], qfl[ks], b1h);
            }
        }

        // ---- causal mask (diagonal tile only) ----
        if (kt == qt) {
            const int rowg0 = qt * 128 + wid * 16 + qr;
            #pragma unroll
            for (int nt = 0; nt < 16; nt++) {
                int colg = kt * 128 + nt * 8 + qc * 2;
                if (colg > rowg0)         s[nt][0] = -INFINITY;
                if (colg + 1 > rowg0)     s[nt][1] = -INFINITY;
                if (colg > rowg0 + 8)     s[nt][2] = -INFINITY;
                if (colg + 1 > rowg0 + 8) s[nt][3] = -INFINITY;
            }
        }

        // ---- online softmax ----
        float mx0 = -INFINITY, mx1 = -INFINITY;
        #pragma unroll
        for (int nt = 0; nt < 16; nt++) {
            mx0 = fmaxf(mx0, fmaxf(s[nt][0], s[nt][1]));
            mx1 = fmaxf(mx1, fmaxf(s[nt][2], s[nt][3]));
        }
        #pragma unroll
        for (int off = 1; off <= 2; off <<= 1) {
            mx0 = fmaxf(mx0, __shfl_xor_sync(0xffffffffu, mx0, off));
            mx1 = fmaxf(mx1, __shfl_xor_sync(0xffffffffu, mx1, off));
        }
        float mn0 = fmaxf(mi0, mx0), mn1 = fmaxf(mi1, mx1);
        float cor0 = __expf(mi0 - mn0), cor1 = __expf(mi1 - mn1);
        float l0 = 0.f, l1 = 0.f;
        #pragma unroll
        for (int nt = 0; nt < 16; nt++) {
            s[nt][0] = __expf(s[nt][0] - mn0);
            s[nt][1] = __expf(s[nt][1] - mn0);
            s[nt][2] = __expf(s[nt][2] - mn1);
            s[nt][3] = __expf(s[nt][3] - mn1);
            l0 += s[nt][0] + s[nt][1];
            l1 += s[nt][2] + s[nt][3];
        }
        #pragma unroll
        for (int off = 1; off <= 2; off <<= 1) {
            l0 += __shfl_xor_sync(0xffffffffu, l0, off);
            l1 += __shfl_xor_sync(0xffffffffu, l1, off);
        }
        li0 = li0 * cor0 + l0;
        li1 = li1 * cor1 + l1;
        mi0 = mn0; mi1 = mn1;
        #pragma unroll
        for (int nt = 0; nt < 16; nt++) {
            o[nt][0] *= cor0; o[nt][1] *= cor0;
            o[nt][2] *= cor1; o[nt][3] *= cor1;
        }

        // ---- O += P V (fp16; V ldmatrix.x4.trans) ----
        #pragma unroll
        for (int ks = 0; ks < 8; ks++) {
            uint32_t pa[4];
            pa[0] = pack_h2(s[2 * ks][0],     s[2 * ks][1]);
            pa[1] = pack_h2(s[2 * ks][2],     s[2 * ks][3]);
            pa[2] = pack_h2(s[2 * ks + 1][0], s[2 * ks + 1][1]);
            pa[3] = pack_h2(s[2 * ks + 1][2], s[2 * ks + 1][3]);
            const uint32_t vrow = (ks * 16 + lrow) * SKS2;
            #pragma unroll
            for (int nt2 = 0; nt2 < 16; nt2 += 2) {
                uint32_t b4[4];
                ldsm4t(b4, uV + (vrow + nt2 * 8 + lcsh) * 2);
                mma16816h(o[nt2],     pa, b4);
                mma16816h(o[nt2 + 1], pa, b4 + 2);
            }
        }

        __syncthreads();
        if (kt + 2 < kt1) {
            attn_issue_tile(base + b * TIL,       g_Khi + (size_t)(kt + 2) * 128 * H, tid);
            attn_issue_tile(base + (2 + b) * TIL, g_Klo + (size_t)(kt + 2) * 128 * H, tid);
            attn_issue_tile(base + (4 + b) * TIL, g_Vh  + (size_t)(kt + 2) * 128 * H, tid);
        }
        CP_COMMIT();
    }

    const int lr0 = wid * 16 + qr;

    if (n_ch == 1) {
        // single chunk: normalize and write output directly
        float inv0 = 1.f / li0, inv1 = 1.f / li1;
        #pragma unroll
        for (int nt = 0; nt < 16; nt++) {
            int c0 = nt * 8 + qc * 2;
            *(float2*)&out[((size_t)qt * 128 + lr0) * H + c0] =
                make_float2(o[nt][0] * inv0, o[nt][1] * inv0);
            *(float2*)&out[((size_t)qt * 128 + lr0 + 8) * H + c0] =
                make_float2(o[nt][2] * inv1, o[nt][3] * inv1);
        }
        return;
    }

    // ---- write partials ----
    const int slot = qt * NCH + ci;
    #pragma unroll
    for (int nt = 0; nt < 16; nt++) {
        int c0 = nt * 8 + qc * 2;
        *(float2*)&g_pO[(size_t)slot * 128 * H + lr0 * H + c0] =
            make_float2(o[nt][0], o[nt][1]);
        *(float2*)&g_pO[(size_t)slot * 128 * H + (lr0 + 8) * H + c0] =
            make_float2(o[nt][2], o[nt][3]);
    }
    if (qc == 0) {
        g_pm[slot * 128 + lr0] = mi0;
        g_pm[slot * 128 + lr0 + 8] = mi1;
        g_pl[slot * 128 + lr0] = li0;
        g_pl[slot * 128 + lr0 + 8] = li1;
    }

    // ---- last block for this qt performs the combine ----
    __threadfence();
    __syncthreads();
    if (tid == 0) {
        int old = atomicAdd(&g_cnt[qt], 1);
        sm_last = (old == n_ch - 1);
    }
    __syncthreads();
    if (!sm_last) return;
    __threadfence();

    {
        const int row = tid >> 1;
        const int col0 = (tid & 1) * 64;
        float m[NCH], l[NCH];
        float M = -INFINITY;
        for (int i = 0; i < n_ch; i++) {
            m[i] = g_pm[(qt * NCH + i) * 128 + row];
            l[i] = g_pl[(qt * NCH + i) * 128 + row];
            M = fmaxf(M, m[i]);
        }
        float L = 0.f, w[NCH];
        for (int i = 0; i < n_ch; i++) {
            w[i] = __expf(m[i] - M);
            L += w[i] * l[i];
        }
        const float invL = 1.f / L;

        #pragma unroll
        for (int c4 = 0; c4 < 16; c4++) {
            float4 acc = make_float4(0.f, 0.f, 0.f, 0.f);
            for (int i = 0; i < n_ch; i++) {
                float4 v = *(const float4*)&g_pO[(size_t)(qt * NCH + i) * 128 * H +
                                                 row * H + col0 + c4 * 4];
                acc.x += w[i] * v.x; acc.y += w[i] * v.y;
                acc.z += w[i] * v.z; acc.w += w[i] * v.w;
            }
            *(float4*)&out[((size_t)qt * 128 + row) * H + col0 + c4 * 4] =
                make_float4(acc.x * invL, acc.y * invL, acc.z * invL, acc.w * invL);
        }
    }
}

// ---------------------------------------------------------------------------
extern "C" void kernel_launch(void* const* d_in, const int* in_sizes, int n_in,
                              void* d_out, int out_size)
{
    const float* x  = (const float*)d_in[0];
    const float* Wq = (const float*)d_in[1];
    const float* Wk = (const float*)d_in[2];
    const float* Wv = (const float*)d_in[3];
    float* out = (float*)d_out;

    cvt_all_kernel<<<(XN + 3 * WN) / 2048, 256>>>(x, Wq, Wk, Wv);

    const int qkv_smem = 2 * QKV_STAGE_ELEMS * (int)sizeof(__nv_bfloat16);
    cudaFuncSetAttribute(qkv_mma_kernel,
                         cudaFuncAttributeMaxDynamicSharedMemorySize, qkv_smem);
    qkv_mma_kernel<<<dim3(32, 3, 3), 256, qkv_smem>>>();

    qkv_reduce_kernel<<<3 * T_TOK * H / 1024, 256>>>();

    const int attn_smem = 6 * (int)TIL;   // 208896
    cudaFuncSetAttribute(attn_partial_kernel,
                         cudaFuncAttributeMaxDynamicSharedMemorySize, attn_smem);
    attn_partial_kernel<<<dim3(NQT, NCH), 256, attn_smem>>>(out);
}

// round 17
// speedup vs baseline: 1.0011x; 1.0011x over previous
#include <cuda_runtime.h>
#include <cuda_bf16.h>
#include <cuda_fp16.h>
#include <math.h>
#include <stdint.h>

#define T_TOK 4096
#define DIM   2048
#define H     128
#define NCH   8
#define NQT   32
#define SKS   40       // qkv smem stride (bf16)
#define SKS2  136      // attn smem stride (bf16/half)
#define SCALE_F 0.08838834764831843f
#define XN (T_TOK * DIM)
#define WN (H * DIM)

// ---------------- device scratch -------------------------------------------
__device__ __nv_bfloat16 g_Xhi[T_TOK * DIM];
__device__ __nv_bfloat16 g_Xlo[T_TOK * DIM];
__device__ __nv_bfloat16 g_Whi[3 * H * DIM];
__device__ __nv_bfloat16 g_Wlo[3 * H * DIM];
__device__ float g_part[9 * T_TOK * H];
__device__ __nv_bfloat16 g_Qhi[T_TOK * H], g_Qlo[T_TOK * H];
__device__ __nv_bfloat16 g_Khi[T_TOK * H], g_Klo[T_TOK * H];
__device__ __half        g_Vh[T_TOK * H];
__device__ float g_pO[NQT * NCH * 128 * H];
__device__ float g_pm[NQT * NCH * 128];
__device__ float g_pl[NQT * NCH * 128];
__device__ int   g_cnt[NQT];

// ---------------- helpers ---------------------------------------------------
__device__ __forceinline__ uint32_t smem_u32(const void* p) {
    uint32_t a;
    asm("{ .reg .u64 t; cvta.to.shared.u64 t, %1; cvt.u32.u64 %0, t; }"
        : "=r"(a) : "l"(p));
    return a;
}
__device__ __forceinline__ void cp16(uint32_t d, const void* s) {
    asm volatile("cp.async.cg.shared.global [%0], [%1], 16;" :: "r"(d), "l"(s));
}
#define CP_COMMIT() asm volatile("cp.async.commit_group;" ::: "memory")
#define CP_WAIT(n)  asm volatile("cp.async.wait_group %0;" :: "n"(n) : "memory")

__device__ __forceinline__ void mma16816(float* c, const uint32_t* a, const uint32_t* b)
{
    asm volatile(
        "mma.sync.aligned.m16n8k16.row.col.f32.bf16.bf16.f32 "
        "{%0,%1,%2,%3}, {%4,%5,%6,%7}, {%8,%9}, {%0,%1,%2,%3};"
        : "+f"(c[0]), "+f"(c[1]), "+f"(c[2]), "+f"(c[3])
        : "r"(a[0]), "r"(a[1]), "r"(a[2]), "r"(a[3]), "r"(b[0]), "r"(b[1]));
}
__device__ __forceinline__ void mma16816h(float* c, const uint32_t* a, const uint32_t* b)
{
    asm volatile(
        "mma.sync.aligned.m16n8k16.row.col.f32.f16.f16.f32 "
        "{%0,%1,%2,%3}, {%4,%5,%6,%7}, {%8,%9}, {%0,%1,%2,%3};"
        : "+f"(c[0]), "+f"(c[1]), "+f"(c[2]), "+f"(c[3])
        : "r"(a[0]), "r"(a[1]), "r"(a[2]), "r"(a[3]), "r"(b[0]), "r"(b[1]));
}
__device__ __forceinline__ void ldsm4(uint32_t* r, uint32_t a)
{
    asm volatile("ldmatrix.sync.aligned.m8n8.x4.shared.b16 {%0,%1,%2,%3}, [%4];"
                 : "=r"(r[0]), "=r"(r[1]), "=r"(r[2]), "=r"(r[3]) : "r"(a));
}
__device__ __forceinline__ void ldsm4t(uint32_t* r, uint32_t a)
{
    asm volatile("ldmatrix.sync.aligned.m8n8.x4.trans.shared.b16 {%0,%1,%2,%3}, [%4];"
                 : "=r"(r[0]), "=r"(r[1]), "=r"(r[2]), "=r"(r[3]) : "r"(a));
}
__device__ __forceinline__ uint32_t pack_hi(float x, float y, uint32_t& lo)
{
    __nv_bfloat16 hx = __float2bfloat16(x);
    __nv_bfloat16 hy = __float2bfloat16(y);
    __nv_bfloat16 lx = __float2bfloat16(x - __bfloat162float(hx));
    __nv_bfloat16 ly = __float2bfloat16(y - __bfloat162float(hy));
    __nv_bfloat162 l2 = __halves2bfloat162(lx, ly);
    lo = *(uint32_t*)&l2;
    __nv_bfloat162 h2 = __halves2bfloat162(hx, hy);
    return *(uint32_t*)&h2;
}
__device__ __forceinline__ uint32_t pack_h2(float x, float y)
{
    __half2 t = __floats2half2_rn(x, y);
    return *(uint32_t*)&t;
}

// ---------------------------------------------------------------------------
// Fused fp32 -> (bf16 hi, lo) split for X, Wq, Wk, Wv in ONE launch.
// Also resets the per-qt combine counters.
// grid = (XN + 3*WN) / 2048 = 4480 blocks.
// ---------------------------------------------------------------------------
__global__ __launch_bounds__(256) void cvt_all_kernel(
    const float* __restrict__ x,  const float* __restrict__ wq,
    const float* __restrict__ wk, const float* __restrict__ wv)
{
    if (blockIdx.x == 0 && threadIdx.x < NQT) g_cnt[threadIdx.x] = 0;

    int i = (blockIdx.x * 256 + threadIdx.x) * 8;
    const float* src;
    __nv_bfloat16 *hi, *lo;
    if (i < XN) {
        src = x + i;
        hi = g_Xhi + i; lo = g_Xlo + i;
    } else {
        int j = i - XN;
        int widx = j / WN;
        int off = j - widx * WN;
        src = (widx == 0 ? wq : widx == 1 ? wk : wv) + off;
        hi = g_Whi + (size_t)widx * WN + off;
        lo = g_Wlo + (size_t)widx * WN + off;
    }
    float4 a = *(const float4*)src;
    float4 b = *(const float4*)(src + 4);
    float xs[8] = {a.x, a.y, a.z, a.w, b.x, b.y, b.z, b.w};
    uint4 hv, lv;
    uint32_t* hp = (uint32_t*)&hv;
    uint32_t* lp = (uint32_t*)&lv;
    #pragma unroll
    for (int j2 = 0; j2 < 4; j2++)
        hp[j2] = pack_hi(xs[2 * j2], xs[2 * j2 + 1], lp[j2]);
    *(uint4*)hi = hv;
    *(uint4*)lo = lv;
}

// ---------------------------------------------------------------------------
// QKV GEMM, bf16x3, K-split-3, cp.async double buffer, ldmatrix frags.
// grid (32, 3, 3).
// ---------------------------------------------------------------------------
#define QKV_STAGE_ELEMS (4 * 128 * SKS)

__global__ __launch_bounds__(256, 2) void qkv_mma_kernel()
{
    extern __shared__ __nv_bfloat16 qsm[];

    const int tid = threadIdx.x;
    const int lid = tid & 31;
    const int wid = tid >> 5;
    const int wm  = wid & 3;
    const int wn  = wid >> 2;
    const int m0  = blockIdx.x * 128;
    const int widx = blockIdx.y;
    const int z    = blockIdx.z;

    const int kbeg = (z == 0) ? 0 : (z == 1) ? 22 : 43;
    const int nkc  = (z == 0) ? 22 : 21;

    const __nv_bfloat16* Ahi = g_Xhi + (size_t)m0 * DIM;
    const __nv_bfloat16* Alo = g_Xlo + (size_t)m0 * DIM;
    const __nv_bfloat16* Bhi = g_Whi + (size_t)widx * H * DIM;
    const __nv_bfloat16* Blo = g_Wlo + (size_t)widx * H * DIM;

    const uint32_t sbase = smem_u32(qsm);
    const uint32_t MAT = 128 * SKS * 2;

    auto issue = [&](int i) {
        uint32_t sb = sbase + (uint32_t)(i & 1) * (4 * MAT);
        int kglob = (kbeg + i) * 32;
        #pragma unroll
        for (int g = 0; g < 2; g++) {
            int idx = tid + g * 256;
            int row = idx >> 2, c8 = (idx & 3) * 8;
            size_t go = (size_t)row * DIM + kglob + c8;
            uint32_t dof = (uint32_t)(row * SKS + c8) * 2;
            cp16(sb + dof,           Ahi + go);
            cp16(sb + MAT + dof,     Alo + go);
            cp16(sb + 2 * MAT + dof, Bhi + go);
            cp16(sb + 3 * MAT + dof, Blo + go);
        }
    };

    float acc[2][8][4];
    #pragma unroll
    for (int im = 0; im < 2; im++)
        #pragma unroll
        for (int in = 0; in < 8; in++)
            #pragma unroll
            for (int q = 0; q < 4; q++) acc[im][in][q] = 0.f;

    issue(0); CP_COMMIT();
    issue(1); CP_COMMIT();

    for (int i = 0; i < nkc; i++) {
        CP_WAIT(1);
        __syncthreads();

        const uint32_t uSt = sbase + (uint32_t)(i & 1) * (4 * MAT);
        const uint32_t uAh = uSt, uAl = uSt + MAT;
        const uint32_t uBh = uSt + 2 * MAT, uBl = uSt + 3 * MAT;

        #pragma unroll
        for (int ks = 0; ks < 2; ks++) {
            const int k0 = ks * 16;
            const uint32_t lrow = (lid & 15);
            const uint32_t lcol = k0 + ((lid >> 4) << 3);
            uint32_t ah[2][4], al[2][4];
            #pragma unroll
            for (int im = 0; im < 2; im++) {
                uint32_t aoff = ((wm * 32 + im * 16 + lrow) * SKS + lcol) * 2;
                ldsm4(ah[im], uAh + aoff);
                ldsm4(al[im], uAl + aoff);
            }
            #pragma unroll
            for (int np = 0; np < 4; np++) {
                uint32_t boff = ((wn * 64 + np * 16 + lrow) * SKS + lcol) * 2;
                uint32_t bh4[4], bl4[4];
                ldsm4(bh4, uBh + boff);
                ldsm4(bl4, uBl + boff);
                uint32_t b0h[2] = {bh4[0], bh4[2]}, b1h[2] = {bh4[1], bh4[3]};
                uint32_t b0l[2] = {bl4[0], bl4[2]}, b1l[2] = {bl4[1], bl4[3]};
                #pragma unroll
                for (int im = 0; im < 2; im++) {
                    mma16816(acc[im][2 * np],     ah[im], b0h);
                    mma16816(acc[im][2 * np],     ah[im], b0l);
                    mma16816(acc[im][2 * np],     al[im], b0h);
                    mma16816(acc[im][2 * np + 1], ah[im], b1h);
                    mma16816(acc[im][2 * np + 1], ah[im], b1l);
                    mma16816(acc[im][2 * np + 1], al[im], b1h);
                }
            }
        }
        __syncthreads();
        if (i + 2 < nkc) issue(i + 2);
        CP_COMMIT();
    }

    float* P = g_part + (size_t)(widx * 3 + z) * T_TOK * H + (size_t)m0 * H;
    #pragma unroll
    for (int im = 0; im < 2; im++) {
        int r0 = wm * 32 + im * 16 + (lid >> 2);
        #pragma unroll
        for (int in = 0; in < 8; in++) {
            int c0 = wn * 64 + in * 8 + (lid & 3) * 2;
            *(float2*)&P[(size_t)r0 * H + c0] =
                make_float2(acc[im][in][0], acc[im][in][1]);
            *(float2*)&P[(size_t)(r0 + 8) * H + c0] =
                make_float2(acc[im][in][2], acc[im][in][3]);
        }
    }
}

// ---------------------------------------------------------------------------
// Reduce K-split partials -> Q/K bf16 hi/lo (Q scaled), V fp16.
// ---------------------------------------------------------------------------
__global__ __launch_bounds__(256) void qkv_reduce_kernel()
{
    const int per = T_TOK * H / 4;
    int i4 = blockIdx.x * 256 + threadIdx.x;
    int widx = i4 / per;
    int off = (i4 - widx * per) * 4;
    const float* p0 = g_part + (size_t)(widx * 3 + 0) * (T_TOK * H) + off;
    const float* p1 = g_part + (size_t)(widx * 3 + 1) * (T_TOK * H) + off;
    const float* p2 = g_part + (size_t)(widx * 3 + 2) * (T_TOK * H) + off;
    float4 a = *(const float4*)p0;
    float4 b = *(const float4*)p1;
    float4 c = *(const float4*)p2;
    float v0 = a.x + b.x + c.x, v1 = a.y + b.y + c.y;
    float v2 = a.z + b.z + c.z, v3 = a.w + b.w + c.w;
    if (widx == 2) {
        *(uint32_t*)&g_Vh[off]     = pack_h2(v0, v1);
        *(uint32_t*)&g_Vh[off + 2] = pack_h2(v2, v3);
    } else {
        float sc = (widx == 0) ? SCALE_F : 1.f;
        v0 *= sc; v1 *= sc; v2 *= sc; v3 *= sc;
        __nv_bfloat16* Ch = widx ? g_Khi : g_Qhi;
        __nv_bfloat16* Cl = widx ? g_Klo : g_Qlo;
        uint32_t lo0, lo1;
        uint32_t h0 = pack_hi(v0, v1, lo0);
        uint32_t h1 = pack_hi(v2, v3, lo1);
        *(uint32_t*)&Ch[off]     = h0;
        *(uint32_t*)&Cl[off]     = lo0;
        *(uint32_t*)&Ch[off + 2] = h1;
        *(uint32_t*)&Cl[off + 2] = lo1;
    }
}

// ---------------------------------------------------------------------------
// Split-KV causal flash attention with in-kernel combine (last block per qt).
// Q frags in registers; K,V double-buffered, issued two tiles ahead.
// ---------------------------------------------------------------------------
#define TIL 34816u

__device__ __forceinline__ void attn_issue_tile(uint32_t dst_base,
                                                const void* src_base, int tid)
{
    #pragma unroll
    for (int j = 0; j < 8; j++) {
        int idx = tid + j * 256;
        int row = idx >> 4, c8 = (idx & 15) * 8;
        cp16(dst_base + (uint32_t)(row * SKS2 + c8) * 2,
             (const char*)src_base + ((size_t)row * H + c8) * 2);
    }
}

__global__ __launch_bounds__(256) void attn_partial_kernel(float* __restrict__ out)
{
    const int qt = blockIdx.x;
    const int ci = blockIdx.y;
    const int n_kt = qt + 1;
    const int kt0 = ci * 4;
    if (kt0 >= n_kt) return;
    const int kt1 = (kt0 + 4 < n_kt) ? kt0 + 4 : n_kt;
    const int n_ch = (n_kt + 3) >> 2;

    extern __shared__ char asm_[];
    const uint32_t base = smem_u32(asm_);
    __shared__ int sm_last;

    const int tid = threadIdx.x;
    const int wid = tid >> 5;
    const int lid = tid & 31;
    const int qr  = lid >> 2;
    const int qc  = lid & 3;
    const uint32_t lrow = (lid & 15);
    const uint32_t lcsh = ((lid >> 4) << 3);

    // ---- prologue: Q -> smem -> registers ----
    attn_issue_tile(base,           g_Qhi + (size_t)qt * 128 * H, tid);
    attn_issue_tile(base + 2 * TIL, g_Qlo + (size_t)qt * 128 * H, tid);
    CP_COMMIT();
    CP_WAIT(0);
    __syncthreads();

    uint32_t qfh[8][4], qfl[8][4];
    #pragma unroll
    for (int ks = 0; ks < 8; ks++) {
        uint32_t qoff = ((wid * 16 + lrow) * SKS2 + ks * 16 + lcsh) * 2;
        ldsm4(qfh[ks], base + qoff);
        ldsm4(qfl[ks], base + 2 * TIL + qoff);
    }
    __syncthreads();

    // ---- issue G(kt0) and G(kt0+1) ----
    attn_issue_tile(base,           g_Khi + (size_t)kt0 * 128 * H, tid);
    attn_issue_tile(base + 2 * TIL, g_Klo + (size_t)kt0 * 128 * H, tid);
    attn_issue_tile(base + 4 * TIL, g_Vh  + (size_t)kt0 * 128 * H, tid);
    CP_COMMIT();
    if (kt0 + 1 < kt1) {
        attn_issue_tile(base + TIL,     g_Khi + (size_t)(kt0 + 1) * 128 * H, tid);
        attn_issue_tile(base + 3 * TIL, g_Klo + (size_t)(kt0 + 1) * 128 * H, tid);
        attn_issue_tile(base + 5 * TIL, g_Vh  + (size_t)(kt0 + 1) * 128 * H, tid);
    }
    CP_COMMIT();

    float o[16][4];
    #pragma unroll
    for (int nt = 0; nt < 16; nt++)
        #pragma unroll
        for (int q = 0; q < 4; q++) o[nt][q] = 0.f;
    float mi0 = -INFINITY, mi1 = -INFINITY, li0 = 0.f, li1 = 0.f;

    for (int kt = kt0; kt < kt1; kt++) {
        const uint32_t b = (uint32_t)(kt - kt0) & 1;
        const uint32_t uKh = base + b * TIL;
        const uint32_t uKl = base + (2 + b) * TIL;
        const uint32_t uV  = base + (4 + b) * TIL;

        CP_WAIT(1);
        __syncthreads();

        // ---- S = Q K^T (bf16x3, Q from regs) ----
        float s[16][4];
        #pragma unroll
        for (int nt = 0; nt < 16; nt++)
            #pragma unroll
            for (int q = 0; q < 4; q++) s[nt][q] = 0.f;

        #pragma unroll
        for (int ks = 0; ks < 8; ks++) {
            const uint32_t lcol = ks * 16 + lcsh;
            #pragma unroll
            for (int np = 0; np < 8; np++) {
                uint32_t koff = ((np * 16 + lrow) * SKS2 + lcol) * 2;
                uint32_t bh4[4], bl4[4];
                ldsm4(bh4, uKh + koff);
                ldsm4(bl4, uKl + koff);
                uint32_t b0h[2] = {bh4[0], bh4[2]}, b1h[2] = {bh4[1], bh4[3]};
                uint32_t b0l[2] = {bl4[0], bl4[2]}, b1l[2] = {bl4[1], bl4[3]};
                mma16816(s[2 * np],     qfh[ks], b0h);
                mma16816(s[2 * np],     qfh[ks], b0l);
                mma16816(s[2 * np],     qfl[ks], b0h);
                mma16816(s[2 * np + 1], qfh[ks], b1h);
                mma16816(s[2 * np + 1], qfh[ks], b1l);
                mma16816(s[2 * np + 1], qfl[ks], b1h);
            }
        }

        // ---- causal mask (diagonal tile only) ----
        if (kt == qt) {
            const int rowg0 = qt * 128 + wid * 16 + qr;
            #pragma unroll
            for (int nt = 0; nt < 16; nt++) {
                int colg = kt * 128 + nt * 8 + qc * 2;
                if (colg > rowg0)         s[nt][0] = -INFINITY;
                if (colg + 1 > rowg0)     s[nt][1] = -INFINITY;
                if (colg > rowg0 + 8)     s[nt][2] = -INFINITY;
                if (colg + 1 > rowg0 + 8) s[nt][3] = -INFINITY;
            }
        }

        // ---- online softmax ----
        float mx0 = -INFINITY, mx1 = -INFINITY;
        #pragma unroll
        for (int nt = 0; nt < 16; nt++) {
            mx0 = fmaxf(mx0, fmaxf(s[nt][0], s[nt][1]));
            mx1 = fmaxf(mx1, fmaxf(s[nt][2], s[nt][3]));
        }
        #pragma unroll
        for (int off = 1; off <= 2; off <<= 1) {
            mx0 = fmaxf(mx0, __shfl_xor_sync(0xffffffffu, mx0, off));
            mx1 = fmaxf(mx1, __shfl_xor_sync(0xffffffffu, mx1, off));
        }
        float mn0 = fmaxf(mi0, mx0), mn1 = fmaxf(mi1, mx1);
        float cor0 = __expf(mi0 - mn0), cor1 = __expf(mi1 - mn1);
        float l0 = 0.f, l1 = 0.f;
        #pragma unroll
        for (int nt = 0; nt < 16; nt++) {
            s[nt][0] = __expf(s[nt][0] - mn0);
            s[nt][1] = __expf(s[nt][1] - mn0);
            s[nt][2] = __expf(s[nt][2] - mn1);
            s[nt][3] = __expf(s[nt][3] - mn1);
            l0 += s[nt][0] + s[nt][1];
            l1 += s[nt][2] + s[nt][3];
        }
        #pragma unroll
        for (int off = 1; off <= 2; off <<= 1) {
            l0 += __shfl_xor_sync(0xffffffffu, l0, off);
            l1 += __shfl_xor_sync(0xffffffffu, l1, off);
        }
        li0 = li0 * cor0 + l0;
        li1 = li1 * cor1 + l1;
        mi0 = mn0; mi1 = mn1;
        #pragma unroll
        for (int nt = 0; nt < 16; nt++) {
            o[nt][0] *= cor0; o[nt][1] *= cor0;
            o[nt][2] *= cor1; o[nt][3] *= cor1;
        }

        // ---- O += P V (fp16; V ldmatrix.x4.trans) ----
        #pragma unroll
        for (int ks = 0; ks < 8; ks++) {
            uint32_t pa[4];
            pa[0] = pack_h2(s[2 * ks][0],     s[2 * ks][1]);
            pa[1] = pack_h2(s[2 * ks][2],     s[2 * ks][3]);
            pa[2] = pack_h2(s[2 * ks + 1][0], s[2 * ks + 1][1]);
            pa[3] = pack_h2(s[2 * ks + 1][2], s[2 * ks + 1][3]);
            const uint32_t vrow = (ks * 16 + lrow) * SKS2;
            #pragma unroll
            for (int nt2 = 0; nt2 < 16; nt2 += 2) {
                uint32_t b4[4];
                ldsm4t(b4, uV + (vrow + nt2 * 8 + lcsh) * 2);
                mma16816h(o[nt2],     pa, b4);
                mma16816h(o[nt2 + 1], pa, b4 + 2);
            }
        }

        __syncthreads();
        if (kt + 2 < kt1) {
            attn_issue_tile(base + b * TIL,       g_Khi + (size_t)(kt + 2) * 128 * H, tid);
            attn_issue_tile(base + (2 + b) * TIL, g_Klo + (size_t)(kt + 2) * 128 * H, tid);
            attn_issue_tile(base + (4 + b) * TIL, g_Vh  + (size_t)(kt + 2) * 128 * H, tid);
        }
        CP_COMMIT();
    }

    const int lr0 = wid * 16 + qr;

    if (n_ch == 1) {
        // single chunk: normalize and write output directly
        float inv0 = 1.f / li0, inv1 = 1.f / li1;
        #pragma unroll
        for (int nt = 0; nt < 16; nt++) {
            int c0 = nt * 8 + qc * 2;
            *(float2*)&out[((size_t)qt * 128 + lr0) * H + c0] =
                make_float2(o[nt][0] * inv0, o[nt][1] * inv0);
            *(float2*)&out[((size_t)qt * 128 + lr0 + 8) * H + c0] =
                make_float2(o[nt][2] * inv1, o[nt][3] * inv1);
        }
        return;
    }

    // ---- write partials ----
    const int slot = qt * NCH + ci;
    #pragma unroll
    for (int nt = 0; nt < 16; nt++) {
        int c0 = nt * 8 + qc * 2;
        *(float2*)&g_pO[(size_t)slot * 128 * H + lr0 * H + c0] =
            make_float2(o[nt][0], o[nt][1]);
        *(float2*)&g_pO[(size_t)slot * 128 * H + (lr0 + 8) * H + c0] =
            make_float2(o[nt][2], o[nt][3]);
    }
    if (qc == 0) {
        g_pm[slot * 128 + lr0] = mi0;
        g_pm[slot * 128 + lr0 + 8] = mi1;
        g_pl[slot * 128 + lr0] = li0;
        g_pl[slot * 128 + lr0 + 8] = li1;
    }

    // ---- last block for this qt performs the combine ----
    __threadfence();
    __syncthreads();
    if (tid == 0) {
        int old = atomicAdd(&g_cnt[qt], 1);
        sm_last = (old == n_ch - 1);
    }
    __syncthreads();
    if (!sm_last) return;
    __threadfence();

    {
        const int row = tid >> 1;
        const int col0 = (tid & 1) * 64;
        float m[NCH], l[NCH];
        float M = -INFINITY;
        for (int i = 0; i < n_ch; i++) {
            m[i] = g_pm[(qt * NCH + i) * 128 + row];
            l[i] = g_pl[(qt * NCH + i) * 128 + row];
            M = fmaxf(M, m[i]);
        }
        float L = 0.f, w[NCH];
        for (int i = 0; i < n_ch; i++) {
            w[i] = __expf(m[i] - M);
            L += w[i] * l[i];
        }
        const float invL = 1.f / L;

        #pragma unroll
        for (int c4 = 0; c4 < 16; c4++) {
            float4 acc = make_float4(0.f, 0.f, 0.f, 0.f);
            for (int i = 0; i < n_ch; i++) {
                float4 v = *(const float4*)&g_pO[(size_t)(qt * NCH + i) * 128 * H +
                                                 row * H + col0 + c4 * 4];
                acc.x += w[i] * v.x; acc.y += w[i] * v.y;
                acc.z += w[i] * v.z; acc.w += w[i] * v.w;
            }
            *(float4*)&out[((size_t)qt * 128 + row) * H + col0 + c4 * 4] =
                make_float4(acc.x * invL, acc.y * invL, acc.z * invL, acc.w * invL);
        }
    }
}

// ---------------------------------------------------------------------------
extern "C" void kernel_launch(void* const* d_in, const int* in_sizes, int n_in,
                              void* d_out, int out_size)
{
    const float* x  = (const float*)d_in[0];
    const float* Wq = (const float*)d_in[1];
    const float* Wk = (const float*)d_in[2];
    const float* Wv = (const float*)d_in[3];
    float* out = (float*)d_out;

    cvt_all_kernel<<<(XN + 3 * WN) / 2048, 256>>>(x, Wq, Wk, Wv);

    const int qkv_smem = 2 * QKV_STAGE_ELEMS * (int)sizeof(__nv_bfloat16);
    cudaFuncSetAttribute(qkv_mma_kernel,
                         cudaFuncAttributeMaxDynamicSharedMemorySize, qkv_smem);
    qkv_mma_kernel<<<dim3(32, 3, 3), 256, qkv_smem>>>();

    qkv_reduce_kernel<<<3 * T_TOK * H / 1024, 256>>>();

    const int attn_smem = 6 * (int)TIL;   // 208896
    cudaFuncSetAttribute(attn_partial_kernel,
                         cudaFuncAttributeMaxDynamicSharedMemorySize, attn_smem);
    attn_partial_kernel<<<dim3(NQT, NCH), 256, attn_smem>>>(out);
}